// round 7
// baseline (speedup 1.0000x reference)
#include <cuda_runtime.h>

// FullyConnectedTensorProduct: B=2^20, MUL=8, DIM=32, 4 paths of 8x8x8.
// R7: weights in __constant__ (LDC broadcast, no crossbar traffic).
// Phase order W1 -> W0 (store o0 early) -> W3 -> W2 (store o1) keeps peak
// register pressure <= 85 so __launch_bounds__(128,6) gives 6 blocks/SM
// (24 warps). W1 dot products packed over v-pairs in f32x2 (-72 fma slots).
// Inputs/outputs transpose-staged through stride-65 padded smem.

typedef unsigned long long u64;

#define ALPHA_F     0.08838834764831845f   /* 1/sqrt(128) */
#define INV_SQRT3_F 0.5773502691896258f
#define EPITCH 65                          /* floats per element row in staging */

__constant__ __align__(16) float cw[2048];  // raw weights (8 KB)

static __device__ __forceinline__ u64 pk2(float lo, float hi) {
    u64 r;
    asm("mov.b64 %0, {%1, %2};"
        : "=l"(r) : "r"(__float_as_uint(lo)), "r"(__float_as_uint(hi)));
    return r;
}
static __device__ __forceinline__ u64 dup2(float x) { return pk2(x, x); }
static __device__ __forceinline__ void upk2(u64 v, float& lo, float& hi) {
    unsigned l_, h_;
    asm("mov.b64 {%0, %1}, %2;" : "=r"(l_), "=r"(h_) : "l"(v));
    lo = __uint_as_float(l_);
    hi = __uint_as_float(h_);
}
static __device__ __forceinline__ u64 ffma2(u64 a, u64 b, u64 c) {
    u64 d;
    asm("fma.rn.f32x2 %0, %1, %2, %3;" : "=l"(d) : "l"(a), "l"(b), "l"(c));
    return d;
}
static __device__ __forceinline__ u64 fmul2(u64 a, u64 b) {
    u64 d;
    asm("mul.rn.f32x2 %0, %1, %2;" : "=l"(d) : "l"(a), "l"(b));
    return d;
}

// a[0..3] += s * cw[off..off+7]  (8 consecutive weights = 4 packed pairs)
static __device__ __forceinline__ void wacc1(int off, u64 s, u64 a[4]) {
    ulonglong2 q0 = *(const ulonglong2*)(cw + off);
    ulonglong2 q1 = *(const ulonglong2*)(cw + off + 4);
    a[0] = ffma2(s, q0.x, a[0]);
    a[1] = ffma2(s, q0.y, a[1]);
    a[2] = ffma2(s, q1.x, a[2]);
    a[3] = ffma2(s, q1.y, a[3]);
}

__global__ __launch_bounds__(128, 6)
void fctp_kernel(const float* __restrict__ x1,
                 const float* __restrict__ x2,
                 float* __restrict__ out)
{
    extern __shared__ __align__(16) float st[];   // 128 * EPITCH staging

    const int tid = threadIdx.x;
    const size_t eBase = (size_t)blockIdx.x * 128;

    // ---- stage inputs: x1*ALPHA at [e*65 + 0..31], x2 at [e*65 + 32..63] ----
    {
        const float4* g1 = (const float4*)(x1 + eBase * 32);
        const float4* g2 = (const float4*)(x2 + eBase * 32);
#pragma unroll
        for (int c = 0; c < 8; c++) {
            int lin = tid + c * 128;          // float4 index in [0,1024)
            int e = lin >> 3, j = (lin & 7) << 2;
            float4 a = g1[lin];
            float* p = st + e * EPITCH + j;
            p[0] = a.x * ALPHA_F; p[1] = a.y * ALPHA_F;
            p[2] = a.z * ALPHA_F; p[3] = a.w * ALPHA_F;
            float4 b = g2[lin];
            float* q = st + e * EPITCH + 32 + j;
            q[0] = b.x; q[1] = b.y; q[2] = b.z; q[3] = b.w;
        }
    }
    __syncthreads();

    float* S = st + tid * EPITCH;

    // ======== phase A: W1: out0[w] += INV3*(v1[u].v2[v]) * W1[u,v,w] ========
    u64 o0[4] = {};
    {
        // v2 packed over v-pairs: pk[vp][k] = (v2[2vp,k], v2[2vp+1,k])
        u64 pk[4][3];
#pragma unroll
        for (int vp = 0; vp < 4; vp++)
#pragma unroll
            for (int k = 0; k < 3; k++)
                pk[vp][k] = pk2(S[40 + 6 * vp + k], S[40 + 6 * vp + 3 + k]);

#pragma unroll
        for (int u = 0; u < 8; u++) {
            u64 vd0 = dup2(S[8 + u * 3 + 0] * INV_SQRT3_F);
            u64 vd1 = dup2(S[8 + u * 3 + 1] * INV_SQRT3_F);
            u64 vd2 = dup2(S[8 + u * 3 + 2] * INV_SQRT3_F);
#pragma unroll
            for (int vp = 0; vp < 4; vp++) {
                u64 p2 = fmul2(vd0, pk[vp][0]);
                p2 = ffma2(vd1, pk[vp][1], p2);
                p2 = ffma2(vd2, pk[vp][2], p2);
                float pa, pb;
                upk2(p2, pa, pb);
                // v = 2*vp : weights at 512 + u*64 + (2vp)*8
                {
                    u64 pd = dup2(pa);
                    const int off = 512 + u * 64 + vp * 16;
                    ulonglong2 q0 = *(const ulonglong2*)(cw + off);
                    ulonglong2 q1 = *(const ulonglong2*)(cw + off + 4);
                    o0[0] = ffma2(pd, q0.x, o0[0]);
                    o0[1] = ffma2(pd, q0.y, o0[1]);
                    o0[2] = ffma2(pd, q1.x, o0[2]);
                    o0[3] = ffma2(pd, q1.y, o0[3]);
                }
                // v = 2*vp+1
                {
                    u64 pd = dup2(pb);
                    const int off = 512 + u * 64 + vp * 16 + 8;
                    ulonglong2 q0 = *(const ulonglong2*)(cw + off);
                    ulonglong2 q1 = *(const ulonglong2*)(cw + off + 4);
                    o0[0] = ffma2(pd, q0.x, o0[0]);
                    o0[1] = ffma2(pd, q0.y, o0[1]);
                    o0[2] = ffma2(pd, q1.x, o0[2]);
                    o0[3] = ffma2(pd, q1.y, o0[3]);
                }
            }
        }
    }

    // ======== dup scalar inputs (survive the early o0 store) ========
    u64 s1d[8], s2d[8];
#pragma unroll
    for (int u = 0; u < 8; u++) s1d[u] = dup2(S[u]);
#pragma unroll
    for (int v = 0; v < 8; v++) s2d[v] = dup2(S[32 + v]);

    // ======== phase B: W0: out0[w] += s2[v] * (sum_u s1[u] * W0[u,v,w]) ========
#pragma unroll
    for (int v = 0; v < 8; v++) {
        u64 a[4] = {};
#pragma unroll
        for (int u = 0; u < 8; u++)
            wacc1(u * 64 + v * 8, s1d[u], a);
#pragma unroll
        for (int i = 0; i < 4; i++) o0[i] = ffma2(s2d[v], a[i], o0[i]);
    }

    // ---- store o0 -> S[0..7] now (s1 lives in s1d regs); frees o0 ----
    {
        float r0, r1;
        upk2(o0[0], r0, r1); S[0] = r0; S[1] = r1;
        upk2(o0[1], r0, r1); S[2] = r0; S[3] = r1;
        upk2(o0[2], r0, r1); S[4] = r0; S[5] = r1;
        upk2(o0[3], r0, r1); S[6] = r0; S[7] = r1;
    }

    // ======== phase C: W3: out1[w,k] += v1[u,k] * (sum_v s2[v] * W3[u,v,w]) ========
    u64 o1[3][4] = {};
#pragma unroll
    for (int u = 0; u < 8; u++) {
        u64 a[4] = {};
#pragma unroll
        for (int v = 0; v < 8; v++)
            wacc1(1536 + u * 64 + v * 8, s2d[v], a);
#pragma unroll
        for (int k = 0; k < 3; k++) {
            u64 t = dup2(S[8 + u * 3 + k]);     // v1 (has ALPHA)
#pragma unroll
            for (int wp = 0; wp < 4; wp++)
                o1[k][wp] = ffma2(t, a[wp], o1[k][wp]);
        }
    }

    // ======== phase D: W2: out1[w,k] += v2[v,k] * (sum_u s1[u] * W2[u,v,w]) ========
#pragma unroll
    for (int v = 0; v < 8; v++) {
        u64 a[4] = {};
#pragma unroll
        for (int u = 0; u < 8; u++)
            wacc1(1024 + u * 64 + v * 8, s1d[u], a);
#pragma unroll
        for (int k = 0; k < 3; k++) {
            u64 t = dup2(S[40 + v * 3 + k]);    // v2
#pragma unroll
            for (int wp = 0; wp < 4; wp++)
                o1[k][wp] = ffma2(t, a[wp], o1[k][wp]);
        }
    }

    // ---- store o1 -> S[8..31] (v1 dead, v2 no longer needed) ----
#pragma unroll
    for (int k = 0; k < 3; k++)
#pragma unroll
        for (int wp = 0; wp < 4; wp++) {
            float lo, hi;
            upk2(o1[k][wp], lo, hi);
            S[8 + (2 * wp)     * 3 + k] = lo;
            S[8 + (2 * wp + 1) * 3 + k] = hi;
        }

    __syncthreads();

    // ---- coalesced drain of S[0..31] per element ----
    {
        float4* go = (float4*)(out + eBase * 32);
#pragma unroll
        for (int c = 0; c < 8; c++) {
            int lin = tid + c * 128;
            int e = lin >> 3, j = (lin & 7) << 2;
            const float* p = st + e * EPITCH + j;
            go[lin] = make_float4(p[0], p[1], p[2], p[3]);
        }
    }
}

extern "C" void kernel_launch(void* const* d_in, const int* in_sizes, int n_in,
                              void* d_out, int out_size)
{
    const float* x1 = (const float*)d_in[0];
    const float* x2 = (const float*)d_in[1];
    const float* wt = (const float*)d_in[2];
    float* out = (float*)d_out;

    // Copy raw weights into constant memory (D2D async: graph-capturable).
    cudaMemcpyToSymbolAsync(cw, wt, 2048 * sizeof(float), 0,
                            cudaMemcpyDeviceToDevice, 0);

    int nelem  = out_size / 32;                     // 2^20
    int blocks = nelem / 128;                       // 128 elements per block
    size_t smem = (128 * EPITCH) * sizeof(float);   // 33280 B

    static bool attr_set = false;
    if (!attr_set) {
        cudaFuncSetAttribute(fctp_kernel,
                             cudaFuncAttributeMaxDynamicSharedMemorySize,
                             (int)smem);
        attr_set = true;
    }
    fctp_kernel<<<blocks, 128, smem>>>(x1, x2, out);
}